// round 9
// baseline (speedup 1.0000x reference)
#include <cuda_runtime.h>
#include <cstdint>

namespace {
constexpr int kB   = 256;
constexpr int kD   = 2048;
constexpr int kS   = 8;
constexpr int kOut = 1000;

constexpr int BM = 32;                 // rows per m-tile
constexpr int BN = 256;                // cols per block
constexpr int BK = 16;                 // K per pipeline stage
constexpr int NSPLIT = 32;
constexpr int KSPLIT = kD / NSPLIT;    // 64
constexpr int NSTG   = KSPLIT / BK;    // 4 stages per block
constexpr int MT = 4;                  // m-tiles per subject (covers counts <= 128)
constexpr int XPAD = 36;               // X k-row stride (16B multiple, bank skew)
constexpr int NTILES = (kOut + BN - 1) / BN;  // 4
}

// Device scratch (allocations forbidden in kernel_launch)
__device__ float g_partial[NSPLIT * kB * kOut];     // 32 MB
__device__ int   g_sem[kS * MT * NTILES];           // split-arrival counters (zero-init;
                                                    // last arrival resets -> replay-safe)

// ---- packed f32x2 helpers ----
__device__ __forceinline__ void ffma2(unsigned long long& d,
                                      unsigned long long a, unsigned long long b) {
    asm("fma.rn.f32x2 %0, %1, %2, %0;" : "+l"(d) : "l"(a), "l"(b));
}
__device__ __forceinline__ unsigned long long dup2(float v) {
    unsigned long long r;
    asm("mov.b64 %0, {%1, %1};" : "=l"(r) : "f"(v));
    return r;
}
__device__ __forceinline__ void unpack2(unsigned long long v, float& lo, float& hi) {
    asm("mov.b64 {%0, %1}, %2;" : "=f"(lo), "=f"(hi) : "l"(v));
}

// ---- cp.async / cache-policy helpers ----
__device__ __forceinline__ unsigned smem_u32(const void* p) {
    return (unsigned)__cvta_generic_to_shared(p);
}
// W stream is single-use: evict_first keeps it from flushing L2.
__device__ __forceinline__ void cp16_ef(unsigned dst, const void* src, int src_sz,
                                        unsigned long long pol) {
    asm volatile("cp.async.cg.shared.global.L2::cache_hint [%0], [%1], 16, %2, %3;"
                 :: "r"(dst), "l"(src), "r"(src_sz), "l"(pol) : "memory");
}
__device__ __forceinline__ void cp_commit() {
    asm volatile("cp.async.commit_group;" ::: "memory");
}
__device__ __forceinline__ void cp_wait1() {
    asm volatile("cp.async.wait_group 1;" ::: "memory");
}
// Partials are re-read within microseconds by the fused reducer: pin in L2.
__device__ __forceinline__ void st128_el(float* p, float a, float b, float c, float d,
                                         unsigned long long pol) {
    asm volatile("st.global.L2::cache_hint.v4.f32 [%0], {%1, %2, %3, %4}, %5;"
                 :: "l"(p), "f"(a), "f"(b), "f"(c), "f"(d), "l"(pol) : "memory");
}

// ---------------------------------------------------------------------------
// Fused GEMM + split-K reduction. grid (n_tile=4, subject=8, mt(4)*split(32)),
// 128 threads. Thread tile 8m x 8n; the 8 n-cols are two float4 groups 128
// cols apart (16B lane stride -> conflict-free LDS.128). W via
// cp.async(evict_first) 2-stage ring; X reg-staged LDG + transpose STS.
// The last split block to finish a (s, mt, ntile) combo sums the 32 L2-hot
// partials + bias and writes out (fixed sp order -> deterministic).
// ---------------------------------------------------------------------------
__global__ __launch_bounds__(128, 5) void gemm_fused_kernel(
    const float* __restrict__ x,              // [B, D]
    const float* __restrict__ W,              // [S, D, OUT]
    const unsigned int* __restrict__ sid_words,
    const float* __restrict__ bias,           // [S, OUT]
    float* __restrict__ out)                  // [B, OUT]
{
    const int s     = blockIdx.y;
    const int mt    = blockIdx.z & (MT - 1);
    const int split = blockIdx.z >> 2;        // MT = 4
    const int m0    = mt * BM;
    const int n0    = blockIdx.x * BN;
    const int kbase = split * KSPLIT;
    const int t     = threadIdx.x;
    const int lane  = t & 31;
    const int warp  = t >> 5;

    __shared__ __align__(16) float Xs[2][BK][XPAD];  // X tile [k][m]
    __shared__ __align__(16) float Ws[2][BK][BN];
    __shared__ int srows[BM];
    __shared__ int chunk_cnt[8];
    __shared__ int hi_flag;
    __shared__ int red_flag;

    // ---- L2 policies ----
    unsigned long long pol_ef, pol_el;
    asm("createpolicy.fractional.L2::evict_first.b64 %0, 1.0;" : "=l"(pol_ef));
    asm("createpolicy.fractional.L2::evict_last.b64 %0, 1.0;"  : "=l"(pol_el));

    // ---- W cp.async roles: 1024 16B chunks per stage, 8 per thread ----
    const int wn_   = (t & 63) * 4;        // col within tile (0..252)
    const int khalf = t >> 6;              // 0/1
    const float* wbase = W + ((size_t)s * kD + kbase) * kOut + n0 + wn_;
    const int wsz = (n0 + wn_ + 3 < kOut) ? 16 : 0;   // zero-fill OOB n-tail

    auto issueW = [&](int st) {
        if (st < NSTG) {
            const int buf = st & 1;
            const float* wsrc = wbase + (size_t)st * BK * kOut;
            #pragma unroll
            for (int q = 0; q < 8; ++q) {
                const int k = 2 * q + khalf;
                cp16_ef(smem_u32(&Ws[buf][k][wn_]), wsrc + (size_t)k * kOut, wsz, pol_ef);
            }
        }
        cp_commit();   // empty tail groups keep wait counts aligned
    };

    // mt==0 blocks are active w.p. ~1 (P(cnt==0) ~ (7/8)^256): prefetch W
    // before bucketing to hide stage-0 DRAM latency behind the prologue.
    if (mt == 0) { issueW(0); issueW(1); }

    // ---- 4-warp parallel bucketing: ordered row list for subject s ----
    // int64-vs-int32 detection: for little-endian int64 ids in [0,8) all odd
    // 32-bit words of the first 256 words are zero.
    if (t < BM) srows[t] = -1;
    if (t == 0) hi_flag = 0;
    __syncthreads();

    const unsigned full = 0xFFFFFFFFu;
    const int b0 = (2 * warp) * 32 + lane;        // chunks 2w, 2w+1
    const int b1 = (2 * warp + 1) * 32 + lane;
    {
        const unsigned any_hi = sid_words[2 * b0 + 1] | sid_words[2 * b1 + 1];
        if (__any_sync(full, any_hi != 0u) && lane == 0) hi_flag = 1;
    }
    __syncthreads();
    const bool is_i32 = (hi_flag != 0);

    const int sb0 = is_i32 ? (int)sid_words[b0] : (int)sid_words[2 * b0];
    const int sb1 = is_i32 ? (int)sid_words[b1] : (int)sid_words[2 * b1];
    const unsigned msk0 = __ballot_sync(full, sb0 == s);
    const unsigned msk1 = __ballot_sync(full, sb1 == s);
    if (lane == 0) {
        chunk_cnt[2 * warp]     = __popc(msk0);
        chunk_cnt[2 * warp + 1] = __popc(msk1);
    }
    __syncthreads();

    int cnt = 0, base0 = 0;
    #pragma unroll
    for (int c = 0; c < 8; ++c) {
        if (c < 2 * warp) base0 += chunk_cnt[c];
        cnt += chunk_cnt[c];
    }
    if (m0 >= cnt) return;                        // uniform exit for empty tiles
    const int base1 = base0 + chunk_cnt[2 * warp];
    const unsigned below = (1u << lane) - 1u;
    if (sb0 == s) {
        const int pos = base0 + __popc(msk0 & below);
        if (pos >= m0 && pos < m0 + BM) srows[pos - m0] = b0;
    }
    if (sb1 == s) {
        const int pos = base1 + __popc(msk1 & below);
        if (pos >= m0 && pos < m0 + BM) srows[pos - m0] = b1;
    }
    __syncthreads();

    if (mt != 0) { issueW(0); issueW(1); }

    // ---- X roles: 128 k-quads per stage, 1 LDG.128 + 4 STS per thread ----
    const int xm_  = t >> 2;               // 0..31
    const int xk4  = (t & 3) * 4;          // k quad within stage
    const int xrow = srows[xm_];
    const float* xptr = (xrow >= 0) ? (x + (size_t)xrow * kD + kbase + xk4)
                                    : nullptr;
    float4 xr = make_float4(0.f, 0.f, 0.f, 0.f);
    if (xptr) xr = *reinterpret_cast<const float4*>(xptr);   // stage 0

    // ---- compute roles: rows [tm, tm+8); cols n0+ln..+3 and n0+128+ln..+3 ----
    const int tm = warp * 8;               // uniform per warp -> broadcast LDS
    const int ln = lane * 4;               // 16B lane stride -> conflict-free

    unsigned long long acc[8][4];          // [m][pairs: A0 A1 B0 B1]
    #pragma unroll
    for (int i = 0; i < 8; ++i)
        #pragma unroll
        for (int j = 0; j < 4; ++j) acc[i][j] = 0ull;

    #pragma unroll
    for (int st = 0; st < NSTG; ++st) {
        const int buf = st & 1;
        cp_wait1();                         // W(st) arrived
        // transpose-store X(st)
        Xs[buf][xk4 + 0][xm_] = xr.x;
        Xs[buf][xk4 + 1][xm_] = xr.y;
        Xs[buf][xk4 + 2][xm_] = xr.z;
        Xs[buf][xk4 + 3][xm_] = xr.w;
        __syncthreads();
        // prefetch X(st+1) into registers
        if (st + 1 < NSTG && xptr)
            xr = *reinterpret_cast<const float4*>(xptr + (st + 1) * BK);

        #pragma unroll
        for (int kk = 0; kk < BK; ++kk) {
            const float4 xa = *reinterpret_cast<const float4*>(&Xs[buf][kk][tm]);
            const float4 xb = *reinterpret_cast<const float4*>(&Xs[buf][kk][tm + 4]);
            const ulonglong2 wA = *reinterpret_cast<const ulonglong2*>(&Ws[buf][kk][ln]);
            const ulonglong2 wB = *reinterpret_cast<const ulonglong2*>(&Ws[buf][kk][128 + ln]);
            const unsigned long long dx[8] = {
                dup2(xa.x), dup2(xa.y), dup2(xa.z), dup2(xa.w),
                dup2(xb.x), dup2(xb.y), dup2(xb.z), dup2(xb.w)};
            #pragma unroll
            for (int i = 0; i < 8; ++i) {
                ffma2(acc[i][0], dx[i], wA.x);
                ffma2(acc[i][1], dx[i], wA.y);
                ffma2(acc[i][2], dx[i], wB.x);
                ffma2(acc[i][3], dx[i], wB.y);
            }
        }
        __syncthreads();                    // all reads of Ws[buf] done
        issueW(st + 2);                     // refill into Ws[buf]
    }

    // ---- epilogue: write split partials L2-pinned ----
    float* pbase = g_partial + (size_t)split * kB * kOut;
    const int nA = n0 + ln;
    const int nB = nA + 128;
    #pragma unroll
    for (int i = 0; i < 8; ++i) {
        const int r = srows[tm + i];
        if (r < 0) continue;
        float vA0, vA1, vA2, vA3, vB0, vB1, vB2, vB3;
        unpack2(acc[i][0], vA0, vA1);
        unpack2(acc[i][1], vA2, vA3);
        unpack2(acc[i][2], vB0, vB1);
        unpack2(acc[i][3], vB2, vB3);
        float* prow = pbase + (size_t)r * kOut;
        if (nA + 3 < kOut) st128_el(prow + nA, vA0, vA1, vA2, vA3, pol_el);
        if (nB + 3 < kOut) st128_el(prow + nB, vB0, vB1, vB2, vB3, pol_el);
    }

    // ---- fused split-K reduction: last arrival sums all 32 partials ----
    __syncthreads();                        // all threads' partial stores issued
    int* sem = &g_sem[(s * MT + mt) * NTILES + blockIdx.x];
    if (t == 0) {
        __threadfence();                    // partials globally visible before count
        const int old = atomicAdd(sem, 1);
        red_flag = (old == NSPLIT - 1);
        if (red_flag) *sem = 0;             // reset for next graph replay
    }
    __syncthreads();
    if (!red_flag) return;
    __threadfence();                        // acquire: see all blocks' partials

    // Reducer: 32 rows x 256 cols = 2048 float4s; 16 per thread, coalesced.
    for (int i = 0; i < 16; ++i) {
        const int pos  = t + 128 * i;
        const int rloc = pos >> 6;          // row within tile
        const int quad = pos & 63;
        const int r = srows[rloc];
        const int n = n0 + quad * 4;
        if (r < 0 || n + 3 >= kOut) continue;   // kOut%4==0: quad fully in/out
        float4 v0 = *reinterpret_cast<const float4*>(bias + (size_t)s * kOut + n);
        float4 v1 = make_float4(0.f, 0.f, 0.f, 0.f);
        const float* p = g_partial + (size_t)r * kOut + n;
        #pragma unroll
        for (int sp = 0; sp < NSPLIT; sp += 2) {
            const float4 a = *reinterpret_cast<const float4*>(p + (size_t)sp * kB * kOut);
            const float4 b = *reinterpret_cast<const float4*>(p + (size_t)(sp + 1) * kB * kOut);
            v0.x += a.x; v0.y += a.y; v0.z += a.z; v0.w += a.w;
            v1.x += b.x; v1.y += b.y; v1.z += b.z; v1.w += b.w;
        }
        v0.x += v1.x; v0.y += v1.y; v0.z += v1.z; v0.w += v1.w;
        *reinterpret_cast<float4*>(out + (size_t)r * kOut + n) = v0;
    }
}

extern "C" void kernel_launch(void* const* d_in, const int* in_sizes, int n_in,
                              void* d_out, int out_size) {
    const float*        x   = (const float*)d_in[0];
    const unsigned int* sid = (const unsigned int*)d_in[1];
    const float*        W   = (const float*)d_in[2];
    const float*        b   = (const float*)d_in[3];
    float*              out = (float*)d_out;

    dim3 grid(NTILES, kS, MT * NSPLIT);   // (4, 8, 128)
    gemm_fused_kernel<<<grid, 128>>>(x, W, sid, b, out);
}

// round 10
// speedup vs baseline: 1.1231x; 1.1231x over previous
#include <cuda_runtime.h>
#include <cstdint>

namespace {
constexpr int kB   = 256;
constexpr int kD   = 2048;
constexpr int kS   = 8;
constexpr int kOut = 1000;

constexpr int BM = 32;                 // rows per m-tile
constexpr int BN = 256;                // cols per block
constexpr int BK = 16;                 // K per pipeline stage
constexpr int NSPLIT = 32;
constexpr int KSPLIT = kD / NSPLIT;    // 64
constexpr int NSTG   = KSPLIT / BK;    // 4 stages per block
constexpr int MT = 4;                  // m-tiles per subject (covers counts <= 128)
constexpr int XPAD = 36;               // X k-row stride (16B multiple, bank skew)
constexpr int NTILES = (kOut + BN - 1) / BN;  // 4
}

// ---- packed f32x2 helpers ----
__device__ __forceinline__ void ffma2(unsigned long long& d,
                                      unsigned long long a, unsigned long long b) {
    asm("fma.rn.f32x2 %0, %1, %2, %0;" : "+l"(d) : "l"(a), "l"(b));
}
__device__ __forceinline__ unsigned long long dup2(float v) {
    unsigned long long r;
    asm("mov.b64 %0, {%1, %1};" : "=l"(r) : "f"(v));
    return r;
}
__device__ __forceinline__ void unpack2(unsigned long long v, float& lo, float& hi) {
    asm("mov.b64 {%0, %1}, %2;" : "=f"(lo), "=f"(hi) : "l"(v));
}

// ---- cp.async / cache-policy helpers ----
__device__ __forceinline__ unsigned smem_u32(const void* p) {
    return (unsigned)__cvta_generic_to_shared(p);
}
// W stream is single-use: evict_first keeps it from flushing L2 (out stays hot).
__device__ __forceinline__ void cp16_ef(unsigned dst, const void* src, int src_sz,
                                        unsigned long long pol) {
    asm volatile("cp.async.cg.shared.global.L2::cache_hint [%0], [%1], 16, %2, %3;"
                 :: "r"(dst), "l"(src), "r"(src_sz), "l"(pol) : "memory");
}
__device__ __forceinline__ void cp_commit() {
    asm volatile("cp.async.commit_group;" ::: "memory");
}
__device__ __forceinline__ void cp_wait1() {
    asm volatile("cp.async.wait_group 1;" ::: "memory");
}

// ---------------------------------------------------------------------------
// Init: out[b, :] = bias[sid[b], :]  (gemm then atomically accumulates).
// Stream order guarantees this completes before the gemm's first add.
// int64-vs-int32 id detection: for little-endian int64 ids in [0,8) all odd
// 32-bit words of the first 256 words are zero.
// ---------------------------------------------------------------------------
__global__ __launch_bounds__(256) void init_out_kernel(
    const unsigned int* __restrict__ sid_words,
    const float* __restrict__ bias,
    float* __restrict__ out)
{
    __shared__ int i32_flag;
    if (threadIdx.x == 0) i32_flag = 0;
    __syncthreads();
    if (threadIdx.x < 128 && sid_words[2 * threadIdx.x + 1] != 0u)
        atomicOr(&i32_flag, 1);
    __syncthreads();

    const int q = blockIdx.x * blockDim.x + threadIdx.x;
    const int base = q * 4;
    if (base >= kB * kOut) return;
    const int b = base / kOut;
    const int n = base - b * kOut;        // kOut % 4 == 0: quad stays in row
    const int sb = i32_flag ? (int)sid_words[b] : (int)sid_words[2 * b];
    *reinterpret_cast<float4*>(out + base) =
        *reinterpret_cast<const float4*>(bias + (size_t)sb * kOut + n);
}

// ---------------------------------------------------------------------------
// GEMM: grid (n_tile=4, subject=8, mt(4)*split(32)=128), 128 threads.
// Identical mainloop to the proven 30.6us config: thread tile 8m x 8n with
// the 8 n-cols as two float4 groups 128 apart (conflict-free LDS.128),
// W via cp.async(evict_first) 2-stage ring, X reg-staged LDG + transpose.
// Epilogue: scalar REDG atomicAdd into out (bias pre-added) -- no partial
// buffer, no reduce kernel, adds spread across the two waves' epilogues.
// ---------------------------------------------------------------------------
__global__ __launch_bounds__(128, 5) void gemm_kernel(
    const float* __restrict__ x,              // [B, D]
    const float* __restrict__ W,              // [S, D, OUT]
    const unsigned int* __restrict__ sid_words,
    float* __restrict__ out)                  // [B, OUT]
{
    const int s     = blockIdx.y;
    const int mt    = blockIdx.z & (MT - 1);
    const int split = blockIdx.z >> 2;        // MT = 4
    const int m0    = mt * BM;
    const int n0    = blockIdx.x * BN;
    const int kbase = split * KSPLIT;
    const int t     = threadIdx.x;
    const int lane  = t & 31;
    const int warp  = t >> 5;

    __shared__ __align__(16) float Xs[2][BK][XPAD];  // X tile [k][m]
    __shared__ __align__(16) float Ws[2][BK][BN];
    __shared__ int srows[BM];
    __shared__ int chunk_cnt[8];
    __shared__ int hi_flag;

    // ---- 4-warp parallel bucketing: ordered row list for subject s ----
    if (t < BM) srows[t] = -1;
    if (t == 0) hi_flag = 0;
    __syncthreads();

    const unsigned full = 0xFFFFFFFFu;
    const int b0 = (2 * warp) * 32 + lane;        // chunks 2w, 2w+1
    const int b1 = (2 * warp + 1) * 32 + lane;
    {
        const unsigned any_hi = sid_words[2 * b0 + 1] | sid_words[2 * b1 + 1];
        if (__any_sync(full, any_hi != 0u) && lane == 0) hi_flag = 1;
    }
    __syncthreads();
    const bool is_i32 = (hi_flag != 0);

    const int sb0 = is_i32 ? (int)sid_words[b0] : (int)sid_words[2 * b0];
    const int sb1 = is_i32 ? (int)sid_words[b1] : (int)sid_words[2 * b1];
    const unsigned msk0 = __ballot_sync(full, sb0 == s);
    const unsigned msk1 = __ballot_sync(full, sb1 == s);
    if (lane == 0) {
        chunk_cnt[2 * warp]     = __popc(msk0);
        chunk_cnt[2 * warp + 1] = __popc(msk1);
    }
    __syncthreads();

    int cnt = 0, base0 = 0;
    #pragma unroll
    for (int c = 0; c < 8; ++c) {
        if (c < 2 * warp) base0 += chunk_cnt[c];
        cnt += chunk_cnt[c];
    }
    if (m0 >= cnt) return;                        // uniform exit for empty tiles
    const int base1 = base0 + chunk_cnt[2 * warp];
    const unsigned below = (1u << lane) - 1u;
    if (sb0 == s) {
        const int pos = base0 + __popc(msk0 & below);
        if (pos >= m0 && pos < m0 + BM) srows[pos - m0] = b0;
    }
    if (sb1 == s) {
        const int pos = base1 + __popc(msk1 & below);
        if (pos >= m0 && pos < m0 + BM) srows[pos - m0] = b1;
    }
    __syncthreads();

    // ---- L2 evict_first policy for the single-use W stream ----
    unsigned long long pol_ef;
    asm("createpolicy.fractional.L2::evict_first.b64 %0, 1.0;" : "=l"(pol_ef));

    // ---- W cp.async roles: 1024 16B chunks per stage, 8 per thread ----
    const int wn_   = (t & 63) * 4;        // col within tile (0..252)
    const int khalf = t >> 6;              // 0/1
    const float* wbase = W + ((size_t)s * kD + kbase) * kOut + n0 + wn_;
    const int wsz = (n0 + wn_ + 3 < kOut) ? 16 : 0;   // zero-fill OOB n-tail

    auto issueW = [&](int st) {
        if (st < NSTG) {
            const int buf = st & 1;
            const float* wsrc = wbase + (size_t)st * BK * kOut;
            #pragma unroll
            for (int q = 0; q < 8; ++q) {
                const int k = 2 * q + khalf;
                cp16_ef(smem_u32(&Ws[buf][k][wn_]), wsrc + (size_t)k * kOut, wsz, pol_ef);
            }
        }
        cp_commit();   // empty tail groups keep wait counts aligned
    };

    // ---- X roles: 128 k-quads per stage, 1 LDG.128 + 4 STS per thread ----
    const int xm_  = t >> 2;               // 0..31
    const int xk4  = (t & 3) * 4;          // k quad within stage
    const int xrow = srows[xm_];
    const float* xptr = (xrow >= 0) ? (x + (size_t)xrow * kD + kbase + xk4)
                                    : nullptr;
    float4 xr = make_float4(0.f, 0.f, 0.f, 0.f);

    issueW(0);
    issueW(1);
    if (xptr) xr = *reinterpret_cast<const float4*>(xptr);   // stage 0

    // ---- compute roles: rows [tm, tm+8); cols n0+ln..+3 and n0+128+ln..+3 ----
    const int tm = warp * 8;               // uniform per warp -> broadcast LDS
    const int ln = lane * 4;               // 16B lane stride -> conflict-free

    unsigned long long acc[8][4];          // [m][pairs: A0 A1 B0 B1]
    #pragma unroll
    for (int i = 0; i < 8; ++i)
        #pragma unroll
        for (int j = 0; j < 4; ++j) acc[i][j] = 0ull;

    #pragma unroll
    for (int st = 0; st < NSTG; ++st) {
        const int buf = st & 1;
        cp_wait1();                         // W(st) arrived
        // transpose-store X(st)
        Xs[buf][xk4 + 0][xm_] = xr.x;
        Xs[buf][xk4 + 1][xm_] = xr.y;
        Xs[buf][xk4 + 2][xm_] = xr.z;
        Xs[buf][xk4 + 3][xm_] = xr.w;
        __syncthreads();
        // prefetch X(st+1) into registers
        if (st + 1 < NSTG && xptr)
            xr = *reinterpret_cast<const float4*>(xptr + (st + 1) * BK);

        #pragma unroll
        for (int kk = 0; kk < BK; ++kk) {
            const float4 xa = *reinterpret_cast<const float4*>(&Xs[buf][kk][tm]);
            const float4 xb = *reinterpret_cast<const float4*>(&Xs[buf][kk][tm + 4]);
            const ulonglong2 wA = *reinterpret_cast<const ulonglong2*>(&Ws[buf][kk][ln]);
            const ulonglong2 wB = *reinterpret_cast<const ulonglong2*>(&Ws[buf][kk][128 + ln]);
            const unsigned long long dx[8] = {
                dup2(xa.x), dup2(xa.y), dup2(xa.z), dup2(xa.w),
                dup2(xb.x), dup2(xb.y), dup2(xb.z), dup2(xb.w)};
            #pragma unroll
            for (int i = 0; i < 8; ++i) {
                ffma2(acc[i][0], dx[i], wA.x);
                ffma2(acc[i][1], dx[i], wA.y);
                ffma2(acc[i][2], dx[i], wB.x);
                ffma2(acc[i][3], dx[i], wB.y);
            }
        }
        __syncthreads();                    // all reads of Ws[buf] done
        issueW(st + 2);                     // refill into Ws[buf]
    }

    // ---- epilogue: REDG accumulate into out (bias pre-added by init) ----
    const int nA = n0 + ln;
    const int nB = nA + 128;
    #pragma unroll
    for (int i = 0; i < 8; ++i) {
        const int r = srows[tm + i];
        if (r < 0) continue;
        float vA0, vA1, vA2, vA3, vB0, vB1, vB2, vB3;
        unpack2(acc[i][0], vA0, vA1);
        unpack2(acc[i][1], vA2, vA3);
        unpack2(acc[i][2], vB0, vB1);
        unpack2(acc[i][3], vB2, vB3);
        float* orow = out + (size_t)r * kOut;
        if (nA + 3 < kOut) {                // kOut%4==0: quad fully in or out
            atomicAdd(orow + nA + 0, vA0);
            atomicAdd(orow + nA + 1, vA1);
            atomicAdd(orow + nA + 2, vA2);
            atomicAdd(orow + nA + 3, vA3);
        }
        if (nB + 3 < kOut) {
            atomicAdd(orow + nB + 0, vB0);
            atomicAdd(orow + nB + 1, vB1);
            atomicAdd(orow + nB + 2, vB2);
            atomicAdd(orow + nB + 3, vB3);
        }
    }
}

extern "C" void kernel_launch(void* const* d_in, const int* in_sizes, int n_in,
                              void* d_out, int out_size) {
    const float*        x   = (const float*)d_in[0];
    const unsigned int* sid = (const unsigned int*)d_in[1];
    const float*        W   = (const float*)d_in[2];
    const float*        b   = (const float*)d_in[3];
    float*              out = (float*)d_out;

    const int nq = (kB * kOut) / 4;       // 64000 quads
    init_out_kernel<<<(nq + 255) / 256, 256>>>(sid, b, out);
    dim3 grid(NTILES, kS, MT * NSPLIT);   // (4, 8, 128)
    gemm_kernel<<<grid, 128>>>(x, W, sid, out);
}

// round 11
// speedup vs baseline: 1.3596x; 1.2106x over previous
#include <cuda_runtime.h>
#include <cstdint>

namespace {
constexpr int kB   = 256;
constexpr int kD   = 2048;
constexpr int kS   = 8;
constexpr int kOut = 1000;

constexpr int BM = 32;                 // rows per m-tile
constexpr int BN = 256;                // cols per block
constexpr int BK = 16;                 // K per pipeline stage
constexpr int NSPLIT = 32;
constexpr int KSPLIT = kD / NSPLIT;    // 64
constexpr int NSTG   = KSPLIT / BK;    // 4 stages per block
constexpr int MT = 4;                  // m-tiles per subject (covers counts <= 128)
constexpr int XPAD = 36;               // X k-row stride (16B multiple, bank skew)
constexpr int NTILES = (kOut + BN - 1) / BN;  // 4
}

// Device scratch (allocations forbidden in kernel_launch)
__device__ float g_partial[NSPLIT * kB * kOut];   // 32 MB

// ---- packed f32x2 helpers ----
__device__ __forceinline__ void ffma2(unsigned long long& d,
                                      unsigned long long a, unsigned long long b) {
    asm("fma.rn.f32x2 %0, %1, %2, %0;" : "+l"(d) : "l"(a), "l"(b));
}
__device__ __forceinline__ unsigned long long dup2(float v) {
    unsigned long long r;
    asm("mov.b64 %0, {%1, %1};" : "=l"(r) : "f"(v));
    return r;
}
__device__ __forceinline__ void unpack2(unsigned long long v, float& lo, float& hi) {
    asm("mov.b64 {%0, %1}, %2;" : "=f"(lo), "=f"(hi) : "l"(v));
}

// ---- cp.async / cache-policy helpers ----
__device__ __forceinline__ unsigned smem_u32(const void* p) {
    return (unsigned)__cvta_generic_to_shared(p);
}
// W stream is single-use: evict_first keeps it from flushing L2.
__device__ __forceinline__ void cp16_ef(unsigned dst, const void* src, int src_sz,
                                        unsigned long long pol) {
    asm volatile("cp.async.cg.shared.global.L2::cache_hint [%0], [%1], 16, %2, %3;"
                 :: "r"(dst), "l"(src), "r"(src_sz), "l"(pol) : "memory");
}
__device__ __forceinline__ void cp_commit() {
    asm volatile("cp.async.commit_group;" ::: "memory");
}
__device__ __forceinline__ void cp_wait1() {
    asm volatile("cp.async.wait_group 1;" ::: "memory");
}
// Partials are re-read within microseconds by the reduce: pin in L2.
__device__ __forceinline__ void st128_el(float* p, float a, float b, float c, float d,
                                         unsigned long long pol) {
    asm volatile("st.global.L2::cache_hint.v4.f32 [%0], {%1, %2, %3, %4}, %5;"
                 :: "l"(p), "f"(a), "f"(b), "f"(c), "f"(d), "l"(pol) : "memory");
}

// ---------------------------------------------------------------------------
// GEMM: grid (n_tile=4, subject=8, mt(4)*split(32)=128), 128 threads.
// (Round-8 configuration, measured ~30.6us — unchanged.)
// Thread tile 8m x 8n; the 8 n-cols are two float4 groups 128 cols apart
// (16B lane stride -> conflict-free LDS.128). W via cp.async(evict_first)
// 2-stage ring; X reg-staged LDG + transpose STS. NSPLIT=32 -> ~1500 active
// blocks = 2 waves so work-stealing smooths the cross-CTA spread.
// ---------------------------------------------------------------------------
__global__ __launch_bounds__(128, 5) void gemm_kernel(
    const float* __restrict__ x,              // [B, D]
    const float* __restrict__ W,              // [S, D, OUT]
    const unsigned int* __restrict__ sid_words)
{
    const int s     = blockIdx.y;
    const int mt    = blockIdx.z & (MT - 1);
    const int split = blockIdx.z >> 2;        // MT = 4
    const int m0    = mt * BM;
    const int n0    = blockIdx.x * BN;
    const int kbase = split * KSPLIT;
    const int t     = threadIdx.x;
    const int lane  = t & 31;
    const int warp  = t >> 5;

    __shared__ __align__(16) float Xs[2][BK][XPAD];  // X tile [k][m]
    __shared__ __align__(16) float Ws[2][BK][BN];
    __shared__ int srows[BM];
    __shared__ int chunk_cnt[8];
    __shared__ int hi_flag;

    // ---- 4-warp parallel bucketing: ordered row list for subject s ----
    // int64-vs-int32 detection: for little-endian int64 ids in [0,8) all odd
    // 32-bit words of the first 256 words are zero.
    if (t < BM) srows[t] = -1;
    if (t == 0) hi_flag = 0;
    __syncthreads();

    const unsigned full = 0xFFFFFFFFu;
    const int b0 = (2 * warp) * 32 + lane;        // chunks 2w, 2w+1
    const int b1 = (2 * warp + 1) * 32 + lane;
    {
        const unsigned any_hi = sid_words[2 * b0 + 1] | sid_words[2 * b1 + 1];
        if (__any_sync(full, any_hi != 0u) && lane == 0) hi_flag = 1;
    }
    __syncthreads();
    const bool is_i32 = (hi_flag != 0);

    const int sb0 = is_i32 ? (int)sid_words[b0] : (int)sid_words[2 * b0];
    const int sb1 = is_i32 ? (int)sid_words[b1] : (int)sid_words[2 * b1];
    const unsigned msk0 = __ballot_sync(full, sb0 == s);
    const unsigned msk1 = __ballot_sync(full, sb1 == s);
    if (lane == 0) {
        chunk_cnt[2 * warp]     = __popc(msk0);
        chunk_cnt[2 * warp + 1] = __popc(msk1);
    }
    __syncthreads();

    int cnt = 0, base0 = 0;
    #pragma unroll
    for (int c = 0; c < 8; ++c) {
        if (c < 2 * warp) base0 += chunk_cnt[c];
        cnt += chunk_cnt[c];
    }
    if (m0 >= cnt) return;                        // uniform exit for empty tiles
    const int base1 = base0 + chunk_cnt[2 * warp];
    const unsigned below = (1u << lane) - 1u;
    if (sb0 == s) {
        const int pos = base0 + __popc(msk0 & below);
        if (pos >= m0 && pos < m0 + BM) srows[pos - m0] = b0;
    }
    if (sb1 == s) {
        const int pos = base1 + __popc(msk1 & below);
        if (pos >= m0 && pos < m0 + BM) srows[pos - m0] = b1;
    }
    __syncthreads();

    // ---- L2 policies ----
    unsigned long long pol_ef, pol_el;
    asm("createpolicy.fractional.L2::evict_first.b64 %0, 1.0;" : "=l"(pol_ef));
    asm("createpolicy.fractional.L2::evict_last.b64 %0, 1.0;"  : "=l"(pol_el));

    // ---- W cp.async roles: 1024 16B chunks per stage, 8 per thread ----
    const int wn_   = (t & 63) * 4;        // col within tile (0..252)
    const int khalf = t >> 6;              // 0/1
    const float* wbase = W + ((size_t)s * kD + kbase) * kOut + n0 + wn_;
    const int wsz = (n0 + wn_ + 3 < kOut) ? 16 : 0;   // zero-fill OOB n-tail

    auto issueW = [&](int st) {
        if (st < NSTG) {
            const int buf = st & 1;
            const float* wsrc = wbase + (size_t)st * BK * kOut;
            #pragma unroll
            for (int q = 0; q < 8; ++q) {
                const int k = 2 * q + khalf;
                cp16_ef(smem_u32(&Ws[buf][k][wn_]), wsrc + (size_t)k * kOut, wsz, pol_ef);
            }
        }
        cp_commit();   // empty tail groups keep wait counts aligned
    };

    // ---- X roles: 128 k-quads per stage, 1 LDG.128 + 4 STS per thread ----
    const int xm_  = t >> 2;               // 0..31
    const int xk4  = (t & 3) * 4;          // k quad within stage
    const int xrow = srows[xm_];
    const float* xptr = (xrow >= 0) ? (x + (size_t)xrow * kD + kbase + xk4)
                                    : nullptr;
    float4 xr = make_float4(0.f, 0.f, 0.f, 0.f);

    issueW(0);
    issueW(1);
    if (xptr) xr = *reinterpret_cast<const float4*>(xptr);   // stage 0

    // ---- compute roles: rows [tm, tm+8); cols n0+ln..+3 and n0+128+ln..+3 ----
    const int tm = warp * 8;               // uniform per warp -> broadcast LDS
    const int ln = lane * 4;               // 16B lane stride -> conflict-free

    unsigned long long acc[8][4];          // [m][pairs: A0 A1 B0 B1]
    #pragma unroll
    for (int i = 0; i < 8; ++i)
        #pragma unroll
        for (int j = 0; j < 4; ++j) acc[i][j] = 0ull;

    #pragma unroll
    for (int st = 0; st < NSTG; ++st) {
        const int buf = st & 1;
        cp_wait1();                         // W(st) arrived
        // transpose-store X(st)
        Xs[buf][xk4 + 0][xm_] = xr.x;
        Xs[buf][xk4 + 1][xm_] = xr.y;
        Xs[buf][xk4 + 2][xm_] = xr.z;
        Xs[buf][xk4 + 3][xm_] = xr.w;
        __syncthreads();
        // prefetch X(st+1) into registers
        if (st + 1 < NSTG && xptr)
            xr = *reinterpret_cast<const float4*>(xptr + (st + 1) * BK);

        #pragma unroll
        for (int kk = 0; kk < BK; ++kk) {
            const float4 xa = *reinterpret_cast<const float4*>(&Xs[buf][kk][tm]);
            const float4 xb = *reinterpret_cast<const float4*>(&Xs[buf][kk][tm + 4]);
            const ulonglong2 wA = *reinterpret_cast<const ulonglong2*>(&Ws[buf][kk][ln]);
            const ulonglong2 wB = *reinterpret_cast<const ulonglong2*>(&Ws[buf][kk][128 + ln]);
            const unsigned long long dx[8] = {
                dup2(xa.x), dup2(xa.y), dup2(xa.z), dup2(xa.w),
                dup2(xb.x), dup2(xb.y), dup2(xb.z), dup2(xb.w)};
            #pragma unroll
            for (int i = 0; i < 8; ++i) {
                ffma2(acc[i][0], dx[i], wA.x);
                ffma2(acc[i][1], dx[i], wA.y);
                ffma2(acc[i][2], dx[i], wB.x);
                ffma2(acc[i][3], dx[i], wB.y);
            }
        }
        __syncthreads();                    // all reads of Ws[buf] done
        issueW(st + 2);                     // refill into Ws[buf]
    }

    // ---- epilogue: write split partials L2-pinned (reduce adds bias) ----
    float* pbase = g_partial + (size_t)split * kB * kOut;
    const int nA = n0 + ln;
    const int nB = nA + 128;
    #pragma unroll
    for (int i = 0; i < 8; ++i) {
        const int r = srows[tm + i];
        if (r < 0) continue;
        float vA0, vA1, vA2, vA3, vB0, vB1, vB2, vB3;
        unpack2(acc[i][0], vA0, vA1);
        unpack2(acc[i][1], vA2, vA3);
        unpack2(acc[i][2], vB0, vB1);
        unpack2(acc[i][3], vB2, vB3);
        float* prow = pbase + (size_t)r * kOut;
        if (nA + 3 < kOut) st128_el(prow + nA, vA0, vA1, vA2, vA3, pol_el);
        if (nB + 3 < kOut) st128_el(prow + nB, vB0, vB1, vB2, vB3, pol_el);
    }
}

// ---------------------------------------------------------------------------
// Reduce v2: 4 threads cooperate per output quad (8 splits each, 8 MLP),
// combined through smem in fixed order -> deterministic, no atomics.
// 1000 blocks x 256 threads = 256k threads (~7 warps/SMSP) so the 32 MB
// partial read runs at bandwidth, not latency.
// ---------------------------------------------------------------------------
__global__ __launch_bounds__(256) void reduce_kernel(
    const unsigned int* __restrict__ sid_words,
    const float* __restrict__ bias,   // [S, OUT]
    float* __restrict__ out)          // [B, OUT]
{
    __shared__ int i32_flag;
    __shared__ __align__(16) float4 buf[3][64];
    if (threadIdx.x == 0) i32_flag = 0;
    __syncthreads();
    if (threadIdx.x < 128 && sid_words[2 * threadIdx.x + 1] != 0u)
        atomicOr(&i32_flag, 1);
    __syncthreads();

    const int t     = threadIdx.x;
    const int group = t >> 6;                       // 0..3 : split groups of 8
    const int qloc  = t & 63;
    const int base  = (blockIdx.x * 64 + qloc) * 4; // kB*kOut/4 = 64000 = 1000*64

    float4 v = make_float4(0.f, 0.f, 0.f, 0.f);
    const float* p = g_partial + base + (size_t)(group * 8) * kB * kOut;
    #pragma unroll
    for (int sp = 0; sp < 8; ++sp) {
        const float4 a = *reinterpret_cast<const float4*>(p + (size_t)sp * kB * kOut);
        v.x += a.x; v.y += a.y; v.z += a.z; v.w += a.w;
    }
    if (group > 0) buf[group - 1][qloc] = v;
    __syncthreads();
    if (group == 0) {
        #pragma unroll
        for (int g = 0; g < 3; ++g) {
            const float4 a = buf[g][qloc];
            v.x += a.x; v.y += a.y; v.z += a.z; v.w += a.w;
        }
        const int b = base / kOut;
        const int n = base - b * kOut;              // kOut % 4 == 0: quad in-row
        const int sb = i32_flag ? (int)sid_words[b] : (int)sid_words[2 * b];
        const float4 bv = *reinterpret_cast<const float4*>(bias + (size_t)sb * kOut + n);
        v.x += bv.x; v.y += bv.y; v.z += bv.z; v.w += bv.w;
        *reinterpret_cast<float4*>(out + base) = v;
    }
}

extern "C" void kernel_launch(void* const* d_in, const int* in_sizes, int n_in,
                              void* d_out, int out_size) {
    const float*        x   = (const float*)d_in[0];
    const unsigned int* sid = (const unsigned int*)d_in[1];
    const float*        W   = (const float*)d_in[2];
    const float*        b   = (const float*)d_in[3];
    float*              out = (float*)d_out;

    dim3 grid(NTILES, kS, MT * NSPLIT);   // (4, 8, 128)
    gemm_kernel<<<grid, 128>>>(x, W, sid);
    reduce_kernel<<<1000, 256>>>(sid, b, out);    // 64000 quads / 64 per block
}